// round 17
// baseline (speedup 1.0000x reference)
#include <cuda_runtime.h>
#include <cuda_bf16.h>

typedef unsigned long long ull;
typedef unsigned int u32;

// ===================== helpers =======================
__device__ __forceinline__ u32 f2tf32(float x) {
    u32 u; asm("cvt.rna.tf32.f32 %0, %1;" : "=r"(u) : "f"(x)); return u;
}
__device__ __forceinline__ float tf32f(float x) {
    return __uint_as_float(f2tf32(x));
}
__device__ __forceinline__ float ex2f(float x) {
    float r; asm("ex2.approx.f32 %0, %1;" : "=f"(r) : "f"(x)); return r;
}
#define MMA_TF32(acc, a0, a1, a2, a3, b0, b1) \
    asm volatile( \
        "mma.sync.aligned.m16n8k8.row.col.f32.tf32.tf32.f32 " \
        "{%0,%1,%2,%3}, {%4,%5,%6,%7}, {%8,%9}, {%0,%1,%2,%3};" \
        : "+f"((acc)[0]), "+f"((acc)[1]), "+f"((acc)[2]), "+f"((acc)[3]) \
        : "r"(a0), "r"(a1), "r"(a2), "r"(a3), "r"(b0), "r"(b1))

#define MMA_BF16(acc, a, b0, b1) \
    asm volatile( \
        "mma.sync.aligned.m16n8k16.row.col.f32.bf16.bf16.f32 " \
        "{%0,%1,%2,%3}, {%4,%5,%6,%7}, {%8,%9}, {%0,%1,%2,%3};" \
        : "+f"((acc)[0]), "+f"((acc)[1]), "+f"((acc)[2]), "+f"((acc)[3]) \
        : "r"((a)[0]), "r"((a)[1]), "r"((a)[2]), "r"((a)[3]), "r"(b0), "r"(b1))

__device__ __forceinline__ void ldsm4(u32* r, u32 addr) {
    asm volatile("ldmatrix.sync.aligned.m8n8.x4.shared.b16 {%0,%1,%2,%3}, [%4];"
        : "=r"(r[0]), "=r"(r[1]), "=r"(r[2]), "=r"(r[3]) : "r"(addr));
}
__device__ __forceinline__ void cpa16(u32 dst, const void* src) {
    asm volatile("cp.async.cg.shared.global [%0], [%1], 16;" :: "r"(dst), "l"(src));
}

// ===================== problem constants ====================================
#define BB    8
#define SS    1024
#define DD    128
#define NH    8
#define HD    16
#define NTOK  8192
#define HFF   512
#define NE    4

// ===================== scratch ==============================================
__device__ float         g_qkv  [NTOK * 384];
__device__ float         g_oB   [NTOK * DD];
__device__ float         g_oS   [NTOK * DD];
__device__ float         g_pre1 [NTOK * DD];
__device__ float         g_h    [NTOK * DD];
__device__ float         g_gates[NTOK * NE];
__device__ float         g_ypart[2 * NTOK * DD];
__device__ __nv_bfloat16 g_w1bf [NE * HFF * DD];
__device__ __nv_bfloat16 g_w2bf [DD * NE * HFF];
__device__ float         g_wqkvB[384 * DD];
__device__ float         g_woB  [DD * DD];
__device__ float         g_woS  [DD * DD];
__device__ float         g_part [128 * 256];
__device__ float         g_nrm  [BB * 256];
__device__ int           g_cntB [BB];
__device__ int           g_flagB[BB];
__device__ int           g_cnt2 = 0;

// ============================================================================
// Prep: Wqkv transpose only.
// ============================================================================
__global__ void __launch_bounds__(256) weight_prep(
    const float* __restrict__ Wqkv, float* __restrict__ wqkvB)
{
    __shared__ float t[32][33];
    const int bid = blockIdx.x;
    const int c0 = (bid % 12) << 5, r0 = (bid / 12) << 5;
    for (int i = threadIdx.x; i < 1024; i += 256) {
        const int r = i >> 5, c = i & 31;
        t[r][c] = Wqkv[(long)(r0 + r) * 384 + c0 + c];
    }
    __syncthreads();
    for (int i = threadIdx.x; i < 1024; i += 256) {
        const int c = i >> 5, r = i & 31;
        wqkvB[(long)(c0 + c) * 128 + r0 + r] = tf32f(t[r][c]);
    }
}

// ============================================================================
// FUSED QKV gemm (1xTF32, 3-stage cp.async) + Wo/W1/W2 transposes on spares.
// Grid 912: [0,384) gemm tiles; [384,912) transposes.
// ============================================================================
__global__ void __launch_bounds__(256) qkv_fused(
    const float* __restrict__ A, const float* __restrict__ Bb,
    const float* __restrict__ bias, float* __restrict__ C,
    const float* __restrict__ Wo, const float* __restrict__ W1,
    const float* __restrict__ W2,
    float* __restrict__ woB, float* __restrict__ woS,
    __nv_bfloat16* __restrict__ w1bf, __nv_bfloat16* __restrict__ w2bf)
{
    extern __shared__ float dynsm[];
    const int tid = threadIdx.x;

    if (blockIdx.x >= 384) {
        int bid = blockIdx.x - 384;
        float (*t)[33] = (float(*)[33])dynsm;
        const float* src; int R, C2, c0, r0, mode;
        float *dB = 0, *dS = 0; __nv_bfloat16* dH = 0;
        if (bid < 16) {
            src = Wo; R = 128; C2 = 128; mode = 0;
            c0 = (bid & 3) << 5; r0 = (bid >> 2) << 5;
            dB = woB; dS = woS;
        } else if (bid < 272) {
            bid -= 16;
            const int e = bid >> 6, rem = bid & 63;
            src = W1 + (long)e * 128 * 512; R = 128; C2 = 512; mode = 1;
            c0 = (rem & 15) << 5; r0 = (rem >> 4) << 5;
            dH = w1bf + (long)e * 512 * 128;
        } else {
            bid -= 272; src = W2; R = 2048; C2 = 128; mode = 1;
            c0 = (bid & 3) << 5; r0 = (bid >> 2) << 5;
            dH = w2bf;
        }
        for (int i = tid; i < 1024; i += 256) {
            const int r = i >> 5, c = i & 31;
            t[r][c] = src[(long)(r0 + r) * C2 + c0 + c];
        }
        __syncthreads();
        for (int i = tid; i < 1024; i += 256) {
            const int c = i >> 5, r = i & 31;
            const float v = t[r][c];
            const long o = (long)(c0 + c) * R + r0 + r;
            if (mode == 0) {
                const u32 big = f2tf32(v);
                dB[o] = __uint_as_float(big);
                dS[o] = __uint_as_float(f2tf32(v - __uint_as_float(big)));
            } else {
                dH[o] = __float2bfloat16(v);
            }
        }
        return;
    }

    const u32 smu = (u32)__cvta_generic_to_shared(dynsm);
    const int wid = tid >> 5, lane = tid & 31;
    const int n0 = (blockIdx.x % 3) << 7, m0 = (blockIdx.x / 3) << 6;
    const int wm = wid >> 2, wn = wid & 3;
    const int lr = lane >> 2, lc = lane & 3;
    const int lda = 128, ldb = 128, ldc = 384;

    const float* Abase = A  + (long)m0 * lda;
    const float* Bbase = Bb + (long)n0 * ldb;

    float acc[2][4][4];
    #pragma unroll
    for (int mi = 0; mi < 2; mi++)
        #pragma unroll
        for (int ni = 0; ni < 4; ni++)
            #pragma unroll
            for (int j = 0; j < 4; j++) acc[mi][ni][j] = 0.f;

#define QSTAGE(KT, S) do { \
    const int _k0 = (KT) << 4; \
    const u32 _sb = smu + (u32)(S) * 15360u; \
    { \
        const int row = tid >> 2, ch = (tid & 3) << 2; \
        cpa16(_sb + (u32)(row * 20 + ch) * 4, Abase + (long)row * lda + _k0 + ch); \
    } \
    _Pragma("unroll") \
    for (int c = 0; c < 2; c++) { \
        const int idx = tid + (c << 8); \
        const int row = idx >> 2, ch = (idx & 3) << 2; \
        cpa16(_sb + 5120u + (u32)(row * 20 + ch) * 4, Bbase + (long)row * ldb + _k0 + ch); \
    } \
    asm volatile("cp.async.commit_group;" ::: "memory"); \
} while (0)

    QSTAGE(0, 0);
    QSTAGE(1, 1);
    for (int kt = 0; kt < 8; kt++) {
        const int s = kt % 3;
        if (kt + 2 < 8) {
            QSTAGE(kt + 2, (kt + 2) % 3);
            asm volatile("cp.async.wait_group 2;" ::: "memory");
        } else if (kt + 1 < 8) {
            asm volatile("cp.async.wait_group 1;" ::: "memory");
        } else {
            asm volatile("cp.async.wait_group 0;" ::: "memory");
        }
        __syncthreads();
        float* AbP = dynsm + s * 3840;
        float* BsP = AbP + 1280;
        #pragma unroll
        for (int k8 = 0; k8 < 2; k8++) {
            const int kc = (k8 << 3) + lc;
            u32 af[2][4];
            #pragma unroll
            for (int mi = 0; mi < 2; mi++) {
                const int r = wm * 32 + mi * 16 + lr;
                af[mi][0] = __float_as_uint(AbP[(r    ) * 20 + kc    ]);
                af[mi][1] = __float_as_uint(AbP[(r + 8) * 20 + kc    ]);
                af[mi][2] = __float_as_uint(AbP[(r    ) * 20 + kc + 4]);
                af[mi][3] = __float_as_uint(AbP[(r + 8) * 20 + kc + 4]);
            }
            #pragma unroll
            for (int ni = 0; ni < 4; ni++) {
                const int nr = wn * 32 + ni * 8 + lr;
                u32 b0 = __float_as_uint(BsP[nr * 20 + kc    ]);
                u32 b1 = __float_as_uint(BsP[nr * 20 + kc + 4]);
                #pragma unroll
                for (int mi = 0; mi < 2; mi++)
                    MMA_TF32(acc[mi][ni], af[mi][0], af[mi][1], af[mi][2], af[mi][3], b0, b1);
            }
        }
        __syncthreads();
    }
#undef QSTAGE

    #pragma unroll
    for (int mi = 0; mi < 2; mi++) {
        const int r0 = m0 + wm * 32 + mi * 16 + lr;
        const int r1 = r0 + 8;
        #pragma unroll
        for (int ni = 0; ni < 4; ni++) {
            const int col = wn * 32 + ni * 8 + (lc << 1);
            float2 bbv = *(const float2*)&bias[n0 + col];
            float v0 = acc[mi][ni][0] + bbv.x, v1 = acc[mi][ni][1] + bbv.y;
            float v2 = acc[mi][ni][2] + bbv.x, v3 = acc[mi][ni][3] + bbv.y;
            *(float2*)&C[(long)r0 * ldc + n0 + col] = make_float2(v0, v1);
            *(float2*)&C[(long)r1 * ldc + n0 + col] = make_float2(v2, v3);
        }
    }
}

// ============================================================================
// 3xTF32 O-proj GEMM, BM=64 x BN=128, BK=16, 3-stage cp.async (92160 B smem).
// part: per-block column stats (block owns 64 tokens). Grid (1, 128).
// ============================================================================
__global__ void __launch_bounds__(256) gemm_mma3(
    const float* __restrict__ Ab, const float* __restrict__ As,
    const float* __restrict__ Bb, const float* __restrict__ Bsm,
    const float* __restrict__ bias, const float* __restrict__ resid,
    float* __restrict__ C,
    int lda, int ldb, int ldc, int Kt, int ldres, float* __restrict__ part)
{
    extern __shared__ float dynsm[];
    const u32 smu = (u32)__cvta_generic_to_shared(dynsm);

    const int tid = threadIdx.x, wid = tid >> 5, lane = tid & 31;
    const int m0 = blockIdx.y << 6, n0 = blockIdx.x << 7;
    const int wm = wid >> 2, wn = wid & 3;
    const int lr = lane >> 2, lc = lane & 3;

    const float* Abase  = Ab  + (long)m0 * lda;
    const float* Asbase = As  + (long)m0 * lda;
    const float* Bbase  = Bb  + (long)n0 * ldb;
    const float* Bsbase = Bsm + (long)n0 * ldb;

    float acc[2][4][4];
    #pragma unroll
    for (int mi = 0; mi < 2; mi++)
        #pragma unroll
        for (int ni = 0; ni < 4; ni++)
            #pragma unroll
            for (int j = 0; j < 4; j++) acc[mi][ni][j] = 0.f;

#define STAGE3(KT, S) do { \
    const int _k0 = (KT) << 4; \
    const u32 _sb = smu + (u32)(S) * 30720u; \
    { \
        const int row = tid >> 2, ch = (tid & 3) << 2; \
        const u32 off = (u32)(row * 20 + ch) * 4; \
        cpa16(_sb + off,        Abase  + (long)row * lda + _k0 + ch); \
        cpa16(_sb + 5120 + off, Asbase + (long)row * lda + _k0 + ch); \
    } \
    _Pragma("unroll") \
    for (int c = 0; c < 2; c++) { \
        const int idx = tid + (c << 8); \
        const int row = idx >> 2, ch = (idx & 3) << 2; \
        const u32 off = (u32)(row * 20 + ch) * 4; \
        cpa16(_sb + 10240 + off, Bbase  + (long)row * ldb + _k0 + ch); \
        cpa16(_sb + 20480 + off, Bsbase + (long)row * ldb + _k0 + ch); \
    } \
    asm volatile("cp.async.commit_group;" ::: "memory"); \
} while (0)

    STAGE3(0, 0);
    STAGE3(1, 1);
    for (int kt = 0; kt < Kt; kt++) {
        const int s = kt % 3;
        if (kt + 2 < Kt) {
            STAGE3(kt + 2, (kt + 2) % 3);
            asm volatile("cp.async.wait_group 2;" ::: "memory");
        } else if (kt + 1 < Kt) {
            asm volatile("cp.async.wait_group 1;" ::: "memory");
        } else {
            asm volatile("cp.async.wait_group 0;" ::: "memory");
        }
        __syncthreads();
        float* AbP = dynsm + s * 7680;
        float* AmP = AbP + 1280;
        float* BsP = AbP + 2560;
        float* BmP = AbP + 5120;
        #pragma unroll
        for (int k8 = 0; k8 < 2; k8++) {
            const int kc = (k8 << 3) + lc;
            u32 af[2][4], am[2][4];
            #pragma unroll
            for (int mi = 0; mi < 2; mi++) {
                const int r = wm * 32 + mi * 16 + lr;
                af[mi][0] = __float_as_uint(AbP[(r    ) * 20 + kc    ]);
                af[mi][1] = __float_as_uint(AbP[(r + 8) * 20 + kc    ]);
                af[mi][2] = __float_as_uint(AbP[(r    ) * 20 + kc + 4]);
                af[mi][3] = __float_as_uint(AbP[(r + 8) * 20 + kc + 4]);
                am[mi][0] = __float_as_uint(AmP[(r    ) * 20 + kc    ]);
                am[mi][1] = __float_as_uint(AmP[(r + 8) * 20 + kc    ]);
                am[mi][2] = __float_as_uint(AmP[(r    ) * 20 + kc + 4]);
                am[mi][3] = __float_as_uint(AmP[(r + 8) * 20 + kc + 4]);
            }
            #pragma unroll
            for (int ni = 0; ni < 4; ni++) {
                const int nr = wn * 32 + ni * 8 + lr;
                u32 b0 = __float_as_uint(BsP[nr * 20 + kc    ]);
                u32 b1 = __float_as_uint(BsP[nr * 20 + kc + 4]);
                u32 s0 = __float_as_uint(BmP[nr * 20 + kc    ]);
                u32 s1 = __float_as_uint(BmP[nr * 20 + kc + 4]);
                #pragma unroll
                for (int mi = 0; mi < 2; mi++) {
                    MMA_TF32(acc[mi][ni], am[mi][0], am[mi][1], am[mi][2], am[mi][3], b0, b1);
                    MMA_TF32(acc[mi][ni], af[mi][0], af[mi][1], af[mi][2], af[mi][3], s0, s1);
                    MMA_TF32(acc[mi][ni], af[mi][0], af[mi][1], af[mi][2], af[mi][3], b0, b1);
                }
            }
        }
        __syncthreads();
    }
#undef STAGE3

    float s8[8], q8[8];
    #pragma unroll
    for (int i = 0; i < 8; i++) { s8[i] = 0.f; q8[i] = 0.f; }

    #pragma unroll
    for (int mi = 0; mi < 2; mi++) {
        const int r0 = m0 + wm * 32 + mi * 16 + lr;
        const int r1 = r0 + 8;
        #pragma unroll
        for (int ni = 0; ni < 4; ni++) {
            const int col = wn * 32 + ni * 8 + (lc << 1);
            float v0 = acc[mi][ni][0], v1 = acc[mi][ni][1];
            float v2 = acc[mi][ni][2], v3 = acc[mi][ni][3];
            if (bias) {
                float2 bbv = *(const float2*)&bias[n0 + col];
                v0 += bbv.x; v1 += bbv.y; v2 += bbv.x; v3 += bbv.y;
            }
            if (resid) {
                float2 ra = *(const float2*)&resid[(long)r0 * ldres + n0 + col];
                float2 rb = *(const float2*)&resid[(long)r1 * ldres + n0 + col];
                v0 += ra.x; v1 += ra.y; v2 += rb.x; v3 += rb.y;
            }
            *(float2*)&C[(long)r0 * ldc + n0 + col] = make_float2(v0, v1);
            *(float2*)&C[(long)r1 * ldc + n0 + col] = make_float2(v2, v3);
            if (part) {
                s8[ni * 2 + 0] += v0 + v2;
                s8[ni * 2 + 1] += v1 + v3;
                q8[ni * 2 + 0] += v0 * v0 + v2 * v2;
                q8[ni * 2 + 1] += v1 * v1 + v3 * v3;
            }
        }
    }

    if (part) {
        #pragma unroll
        for (int i = 0; i < 8; i++) {
            s8[i] += __shfl_xor_sync(0xffffffffu, s8[i], 4);
            s8[i] += __shfl_xor_sync(0xffffffffu, s8[i], 8);
            s8[i] += __shfl_xor_sync(0xffffffffu, s8[i], 16);
            q8[i] += __shfl_xor_sync(0xffffffffu, q8[i], 4);
            q8[i] += __shfl_xor_sync(0xffffffffu, q8[i], 8);
            q8[i] += __shfl_xor_sync(0xffffffffu, q8[i], 16);
        }
        float* ssum = dynsm;
        float* ssq  = dynsm + 256;
        __syncthreads();
        if (lr == 0) {
            #pragma unroll
            for (int i = 0; i < 8; i++) {
                const int col = wn * 32 + (i >> 1) * 8 + (lc << 1) + (i & 1);
                ssum[wm * 128 + col] = s8[i];
                ssq [wm * 128 + col] = q8[i];
            }
        }
        __syncthreads();
        if (tid < 128) {
            part[blockIdx.y * 256 + tid]       = ssum[tid] + ssum[128 + tid];
            part[blockIdx.y * 256 + 128 + tid] = ssq[tid]  + ssq[128 + tid];
        }
    }
}

// ============================================================================
// FUSED MoE + norm-1 apply + gating (round-15 version; stats from 16 chunks).
// ============================================================================
#define SA_OFF  0u
#define SW1_OFF 17408u
#define SW2_OFF 52224u
#define SH_OFF  89088u
#define MOE_SMEM 107520

__global__ void __launch_bounds__(256) moe_fused(
    const float* __restrict__ pre1, const float* __restrict__ part,
    const float* __restrict__ n1w, const float* __restrict__ n1b,
    const float* __restrict__ wg,
    const __nv_bfloat16* __restrict__ w1bf, const __nv_bfloat16* __restrict__ w2bf,
    const float* __restrict__ b1,
    float* __restrict__ hout, float* __restrict__ gatesOut,
    float* __restrict__ ypart)
{
    extern __shared__ char msm[];
    const u32 smu = (u32)__cvta_generic_to_shared(msm);

    const int tid = threadIdx.x, wid = tid >> 5, lane = tid & 31;
    const int lr = lane >> 2, lc = lane & 3, sel = lane >> 3;
    const int wm = wid >> 1, wn = wid & 1;
    const int m0 = blockIdx.x << 6;
    const int e0 = blockIdx.y << 1;
    const int b  = m0 >> 10;

#define MSTAGE(IT, S) do { \
    const int _e = e0 + ((IT) >> 3), _c = (IT) & 7; \
    const __nv_bfloat16* _w1 = w1bf + (long)((_e << 9) + (_c << 6)) * 128; \
    const __nv_bfloat16* _w2 = w2bf + (_e << 9) + (_c << 6); \
    _Pragma("unroll") \
    for (int j = 0; j < 4; j++) { \
        const int idx = tid + (j << 8); \
        const int r1 = idx >> 4, ch1 = (idx & 15) << 3; \
        cpa16(smu + SW1_OFF + (S) * 17408u + (u32)(r1 * 136 + ch1) * 2, \
              _w1 + (long)r1 * 128 + ch1); \
        const int r2 = idx >> 3, ch2 = (idx & 7) << 3; \
        cpa16(smu + SW2_OFF + (S) * 18432u + (u32)(r2 * 72 + ch2) * 2, \
              _w2 + (long)r2 * 2048 + ch2); \
    } \
    asm volatile("cp.async.commit_group;" ::: "memory"); \
} while (0)

    MSTAGE(0, 0);

    float* ovl    = (float*)(msm + SW1_OFF + 17408u);
    float* scA    = ovl;
    float* sfA    = ovl + 128;
    float* wgS    = ovl + 256;
    float* gatesS = ovl + 768;
    wgS[tid] = wg[tid];
    wgS[tid + 256] = wg[tid + 256];
    if (tid < DD) {
        const int d = tid;
        float s = 0.f, q = 0.f;
        for (int c = 0; c < 16; c++) {
            const float* p = part + (long)(b * 16 + c) * 256;
            s += p[d]; q += p[DD + d];
        }
        float mean = s * (1.f / 1024.f);
        float var  = q * (1.f / 1024.f) - mean * mean;
        float inv  = rsqrtf(var + 1e-5f);
        float scale = n1w[d] * inv;
        scA[d] = scale;
        sfA[d] = n1b[d] - mean * scale;
    }
    __syncthreads();

    {
        const int c4 = tid & 31, rg = tid >> 5;
        const int c0 = c4 << 2;
        for (int r = rg; r < 64; r += 8) {
            const long tok = m0 + r;
            float4 v = *(const float4*)(pre1 + tok * DD + c0);
            float4 o;
            o.x = v.x * scA[c0 + 0] + sfA[c0 + 0];
            o.y = v.y * scA[c0 + 1] + sfA[c0 + 1];
            o.z = v.z * scA[c0 + 2] + sfA[c0 + 2];
            o.w = v.w * scA[c0 + 3] + sfA[c0 + 3];
            if (e0 == 0) *(float4*)(hout + tok * DD + c0) = o;
            __nv_bfloat162 p0 = __floats2bfloat162_rn(o.x, o.y);
            __nv_bfloat162 p1 = __floats2bfloat162_rn(o.z, o.w);
            asm volatile("st.shared.v2.b32 [%0], {%1, %2};" ::
                "r"(smu + SA_OFF + (u32)(r * 136 + c0) * 2),
                "r"(*(u32*)&p0), "r"(*(u32*)&p1));
            float l0 = o.x * wgS[(c0 + 0) * NE + 0] + o.y * wgS[(c0 + 1) * NE + 0]
                     + o.z * wgS[(c0 + 2) * NE + 0] + o.w * wgS[(c0 + 3) * NE + 0];
            float l1 = o.x * wgS[(c0 + 0) * NE + 1] + o.y * wgS[(c0 + 1) * NE + 1]
                     + o.z * wgS[(c0 + 2) * NE + 1] + o.w * wgS[(c0 + 3) * NE + 1];
            float l2 = o.x * wgS[(c0 + 0) * NE + 2] + o.y * wgS[(c0 + 1) * NE + 2]
                     + o.z * wgS[(c0 + 2) * NE + 2] + o.w * wgS[(c0 + 3) * NE + 2];
            float l3 = o.x * wgS[(c0 + 0) * NE + 3] + o.y * wgS[(c0 + 1) * NE + 3]
                     + o.z * wgS[(c0 + 2) * NE + 3] + o.w * wgS[(c0 + 3) * NE + 3];
            #pragma unroll
            for (int off = 16; off; off >>= 1) {
                l0 += __shfl_xor_sync(0xffffffffu, l0, off);
                l1 += __shfl_xor_sync(0xffffffffu, l1, off);
                l2 += __shfl_xor_sync(0xffffffffu, l2, off);
                l3 += __shfl_xor_sync(0xffffffffu, l3, off);
            }
            if (c4 == 0) {
                float lg[4] = {l0, l1, l2, l3};
                int i1 = 0; float v1 = lg[0];
                #pragma unroll
                for (int e = 1; e < 4; e++) if (lg[e] > v1) { v1 = lg[e]; i1 = e; }
                int i2 = 0; float v2 = -3e38f;
                #pragma unroll
                for (int e = 0; e < 4; e++) if (e != i1 && lg[e] > v2) { v2 = lg[e]; i2 = e; }
                float e2  = expf(v2 - v1);
                float inv = 1.f / (1.f + e2);
                #pragma unroll
                for (int e = 0; e < 4; e++) {
                    const float gv = (e == i1) ? inv : ((e == i2) ? e2 * inv : 0.f);
                    gatesS[r * NE + e] = gv;
                    if (e0 == 0) gatesOut[tok * NE + e] = gv;
                }
            }
        }
    }
    __syncthreads();

    const int row0 = wm * 16 + lr;
    const float g00 = gatesS[(row0    ) * NE + e0];
    const float g01 = gatesS[(row0    ) * NE + e0 + 1];
    const float g10 = gatesS[(row0 + 8) * NE + e0];
    const float g11 = gatesS[(row0 + 8) * NE + e0 + 1];
    __syncthreads();

    const u32 aoff1 = (u32)((wm * 16 + (lane & 7) + ((sel & 1) << 3)) * 136
                            + ((sel >> 1) << 3)) * 2;
    u32 boff1[2];
    #pragma unroll
    for (int nb = 0; nb < 2; nb++)
        boff1[nb] = (u32)((wn * 32 + nb * 16 + ((sel >> 1) << 3) + (lane & 7)) * 136
                          + ((sel & 1) << 3)) * 2;
    const u32 aoff2 = (u32)((wm * 16 + (lane & 7) + ((sel & 1) << 3)) * 72
                            + ((sel >> 1) << 3)) * 2;
    u32 boff2[4];
    #pragma unroll
    for (int nb = 0; nb < 4; nb++)
        boff2[nb] = (u32)((wn * 64 + nb * 16 + ((sel >> 1) << 3) + (lane & 7)) * 72
                          + ((sel & 1) << 3)) * 2;

    float acc2[8][4];
    #pragma unroll
    for (int ni = 0; ni < 8; ni++)
        #pragma unroll
        for (int j = 0; j < 4; j++) acc2[ni][j] = 0.f;

    const int gtok0 = m0 + row0, gtok1 = gtok0 + 8;

    for (int it = 0; it < 16; it++) {
        const int s = it & 1;
        const int e = e0 + (it >> 3), c = it & 7;
        if (it + 1 < 16) {
            MSTAGE(it + 1, s ^ 1);
            asm volatile("cp.async.wait_group 1;" ::: "memory");
        } else {
            asm volatile("cp.async.wait_group 0;" ::: "memory");
        }
        __syncthreads();

        const u32 w1b = smu + SW1_OFF + s * 17408u;
        const u32 ab  = smu + SA_OFF;
        float acc1[4][4];
        #pragma unroll
        for (int ni = 0; ni < 4; ni++)
            #pragma unroll
            for (int j = 0; j < 4; j++) acc1[ni][j] = 0.f;
        #pragma unroll
        for (int k16 = 0; k16 < 8; k16++) {
            u32 a[4];
            ldsm4(a, ab + aoff1 + k16 * 32);
            #pragma unroll
            for (int nb = 0; nb < 2; nb++) {
                u32 bf[4];
                ldsm4(bf, w1b + boff1[nb] + k16 * 32);
                MMA_BF16(acc1[2 * nb    ], a, bf[0], bf[1]);
                MMA_BF16(acc1[2 * nb + 1], a, bf[2], bf[3]);
            }
        }
        const float g0 = (it >> 3) ? g01 : g00;
        const float g1 = (it >> 3) ? g11 : g10;
        const u32 hbse = smu + SH_OFF + s * 9216u;
        #pragma unroll
        for (int ni = 0; ni < 4; ni++) {
            const int col = wn * 32 + ni * 8 + (lc << 1);
            const float bb0 = __ldg(&b1[(e << 9) + (c << 6) + col]);
            const float bb1 = __ldg(&b1[(e << 9) + (c << 6) + col + 1]);
            float v0 = fmaxf(acc1[ni][0] + bb0, 0.f) * g0;
            float v1 = fmaxf(acc1[ni][1] + bb1, 0.f) * g0;
            float v2 = fmaxf(acc1[ni][2] + bb0, 0.f) * g1;
            float v3 = fmaxf(acc1[ni][3] + bb1, 0.f) * g1;
            __nv_bfloat162 p0 = __floats2bfloat162_rn(v0, v1);
            __nv_bfloat162 p1 = __floats2bfloat162_rn(v2, v3);
            asm volatile("st.shared.b32 [%0], %1;" ::
                "r"(hbse + (u32)(row0 * 72 + col) * 2), "r"(*(u32*)&p0));
            asm volatile("st.shared.b32 [%0], %1;" ::
                "r"(hbse + (u32)((row0 + 8) * 72 + col) * 2), "r"(*(u32*)&p1));
        }
        asm volatile("bar.sync %0, 64;" :: "r"(wm + 1) : "memory");

        const u32 w2b = smu + SW2_OFF + s * 18432u;
        #pragma unroll
        for (int k16 = 0; k16 < 4; k16++) {
            u32 a[4];
            ldsm4(a, hbse + aoff2 + k16 * 32);
            #pragma unroll
            for (int nb = 0; nb < 4; nb++) {
                u32 bf[4];
                ldsm4(bf, w2b + boff2[nb] + k16 * 32);
                MMA_BF16(acc2[2 * nb    ], a, bf[0], bf[1]);
                MMA_BF16(acc2[2 * nb + 1], a, bf[2], bf[3]);
            }
        }
        __syncthreads();
    }
#undef MSTAGE

    float* yz = ypart + (long)blockIdx.y * NTOK * DD;
    #pragma unroll
    for (int ni = 0; ni < 8; ni++) {
        const int col = wn * 64 + ni * 8 + (lc << 1);
        *(float2*)&yz[(long)gtok0 * DD + col] = make_float2(acc2[ni][0], acc2[ni][1]);
        *(float2*)&yz[(long)gtok1 * DD + col] = make_float2(acc2[ni][2], acc2[ni][3]);
    }
}

// ============================================================================
// MMA flash attention (unchanged).
// ============================================================================
#define VSR 1044
#define PSR 132
#define SM_K 0
#define SM_V (1024 * 16)
#define SM_P (SM_V + 16 * VSR)
#define ATTN_SMEM ((SM_P + 128 * PSR) * 4)

__global__ void __launch_bounds__(256) attn_mma(const float* __restrict__ qkv,
                                                float* __restrict__ oB,
                                                float* __restrict__ oS)
{
    extern __shared__ float sm[];
    const int bh = blockIdx.x, b = bh >> 3, h = bh & 7;
    const int tid = threadIdx.x, wid = tid >> 5, lane = tid & 31;
    const int lr = lane >> 2, lc = lane & 3;
    const float* qkvb = qkv + (long)b * SS * 384;
    const int qoff = h * HD, koff = DD + h * HD, voff = 2 * DD + h * HD;
    const float QSCL = 0.25f * 1.4426950408889634f;

    for (int i = tid; i < SS * 4; i += 256) {
        const int s = i >> 2, c4 = i & 3;
        float4 v = *(const float4*)(qkvb + (long)s * 384 + koff + (c4 << 2));
        float* kp = &sm[SM_K + (s << 4)];
        kp[c4]      = tf32f(v.x);
        kp[c4 + 4]  = tf32f(v.y);
        kp[c4 + 8]  = tf32f(v.z);
        kp[c4 + 12] = tf32f(v.w);
        float4 w = *(const float4*)(qkvb + (long)s * 384 + voff + (c4 << 2));
        const int colp = (s & ~7) + ((s & 3) << 1) + ((s & 7) >> 2);
        sm[SM_V + ((c4 << 2) + 0) * VSR + colp] = tf32f(w.x);
        sm[SM_V + ((c4 << 2) + 1) * VSR + colp] = tf32f(w.y);
        sm[SM_V + ((c4 << 2) + 2) * VSR + colp] = tf32f(w.z);
        sm[SM_V + ((c4 << 2) + 3) * VSR + colp] = tf32f(w.w);
    }
    __syncthreads();

    const int wq = wid << 4;
    float* Prow0 = &sm[SM_P + (wq + lr) * PSR];
    float* Prow1 = Prow0 + 8 * PSR;

    for (int j = 0; j < 4; j++) {
        const int qt = (blockIdx.y << 2) + j;

        const float* qp0 = qkvb + (long)(qt * 128 + wq + lr) * 384 + qoff;
        const float* qp1 = qp0 + 8 * 384;
        u32 qf[2][4];
        #pragma unroll
        for (int k8 = 0; k8 < 2; k8++) {
            const int c = (k8 << 3) + lc;
            qf[k8][0] = f2tf32(__ldg(&qp0[c])     * QSCL);
            qf[k8][1] = f2tf32(__ldg(&qp1[c])     * QSCL);
            qf[k8][2] = f2tf32(__ldg(&qp0[c + 4]) * QSCL);
            qf[k8][3] = f2tf32(__ldg(&qp1[c + 4]) * QSCL);
        }

        float oacc[2][4];
        #pragma unroll
        for (int t = 0; t < 2; t++)
            #pragma unroll
            for (int jj = 0; jj < 4; jj++) oacc[t][jj] = 0.f;
        float sl0 = 0.f, sl1 = 0.f;

        for (int kt = 0; kt < 8; kt++) {
            #pragma unroll
            for (int ni = 0; ni < 16; ni++) {
                const int krow = kt * 128 + ni * 8 + lr;
                float4 kv = *(const float4*)&sm[SM_K + (krow << 4) + (lc << 2)];
                float sacc[4] = {0.f, 0.f, 0.f, 0.f};
                MMA_TF32(sacc, qf[0][0], qf[0][1], qf[0][2], qf[0][3],
                         __float_as_uint(kv.x), __float_as_uint(kv.y));
                MMA_TF32(sacc, qf[1][0], qf[1][1], qf[1][2], qf[1][3],
                         __float_as_uint(kv.z), __float_as_uint(kv.w));
                const float p0 = ex2f(sacc[0]), p1 = ex2f(sacc[1]);
                const float p2 = ex2f(sacc[2]), p3 = ex2f(sacc[3]);
                sl0 += p0 + p1;
                sl1 += p2 + p3;
                const int col = ni * 8 + (lc << 1);
                *(float2*)&Prow0[col] = make_float2(p0, p1);
                *(float2*)&Prow1[col] = make_float2(p2, p3);
            }
            __syncwarp();
            #pragma unroll
            for (int k8 = 0; k8 < 16; k8++) {
                const int kc2 = (k8 << 3) + lc;
                u32 a0 = __float_as_uint(Prow0[kc2]);
                u32 a1 = __float_as_uint(Prow1[kc2]);
                u32 a2 = __float_as_uint(Prow0[kc2 + 4]);
                u32 a3 = __float_as_uint(Prow1[kc2 + 4]);
                const int kgb = kt * 128 + (k8 << 3) + (lc << 1);
                float2 va = *(const float2*)&sm[SM_V + (lr    ) * VSR + kgb];
                float2 vb = *(const float2*)&sm[SM_V + (lr + 8) * VSR + kgb];
                MMA_TF32(oacc[0], a0, a1, a2, a3,
                         __float_as_uint(va.x), __float_as_uint(va.y));
                MMA_TF32(oacc[1], a0, a1, a2, a3,
                         __float_as_uint(vb.x), __float_as_uint(vb.y));
            }
            __syncwarp();
        }

        float s0 = sl0, s1 = sl1;
        s0 += __shfl_xor_sync(0xffffffffu, s0, 1);
        s0 += __shfl_xor_sync(0xffffffffu, s0, 2);
        s1 += __shfl_xor_sync(0xffffffffu, s1, 1);
        s1 += __shfl_xor_sync(0xffffffffu, s1, 2);
        const float i0 = 1.f / s0, i1 = 1.f / s1;

        const long r0 = (long)(b * SS + qt * 128 + wq + lr);
        const long r1 = r0 + 8;
        #pragma unroll
        for (int t = 0; t < 2; t++) {
            const int col = h * HD + t * 8 + (lc << 1);
            float w0 = oacc[t][0] * i0, w1 = oacc[t][1] * i0;
            float w2 = oacc[t][2] * i1, w3 = oacc[t][3] * i1;
            float bb0 = tf32f(w0), bb1 = tf32f(w1), bb2 = tf32f(w2), bb3 = tf32f(w3);
            *(float2*)&oB[r0 * DD + col] = make_float2(bb0, bb1);
            *(float2*)&oB[r1 * DD + col] = make_float2(bb2, bb3);
            *(float2*)&oS[r0 * DD + col] = make_float2(tf32f(w0 - bb0), tf32f(w1 - bb1));
            *(float2*)&oS[r1 * DD + col] = make_float2(tf32f(w2 - bb2), tf32f(w3 - bb3));
        }
    }
}

// ============================================================================
// FUSED final: add + norm-2 stats + per-batch grid-sync + apply (unchanged).
// ============================================================================
__global__ void __launch_bounds__(256) add_norm2(
    const float* __restrict__ yp, const float* __restrict__ h,
    const float* __restrict__ gates, const float* __restrict__ b2,
    const float* __restrict__ n2w, const float* __restrict__ n2b,
    float* __restrict__ part, float* __restrict__ out)
{
    const int b = blockIdx.y, chunk = blockIdx.x;
    __shared__ float b2s[NE * DD];
    b2s[threadIdx.x] = b2[threadIdx.x];
    b2s[threadIdx.x + 256] = b2[threadIdx.x + 256];
    __syncthreads();
    const long row0 = (long)b * SS + chunk * 64;
    const int c4 = threadIdx.x & 31, rg = threadIdx.x >> 5;
    const int c0 = c4 << 2;

    float4 vals[8];
    float4 s = make_float4(0.f, 0.f, 0.f, 0.f), q = s;
    #pragma unroll
    for (int i = 0; i < 8; i++) {
        const int r = rg + i * 8;
        const long tok = row0 + r;
        const long idx = tok * DD + c0;
        const float* g = gates + tok * NE;
        const float g0 = g[0], g1 = g[1], g2 = g[2], g3 = g[3];
        float4 v  = *(const float4*)(yp + idx);
        float4 v1 = *(const float4*)(yp + (long)NTOK * DD + idx);
        float4 hv = *(const float4*)(h + idx);
        float4 o;
        o.x = v.x + v1.x + hv.x
            + g0 * b2s[c0 + 0] + g1 * b2s[DD + c0 + 0] + g2 * b2s[2 * DD + c0 + 0] + g3 * b2s[3 * DD + c0 + 0];
        o.y = v.y + v1.y + hv.y
            + g0 * b2s[c0 + 1] + g1 * b2s[DD + c0 + 1] + g2 * b2s[2 * DD + c0 + 1] + g3 * b2s[3 * DD + c0 + 1];
        o.z = v.z + v1.z + hv.z
            + g0 * b2s[c0 + 2] + g1 * b2s[DD + c0 + 2] + g2 * b2s[2 * DD + c0 + 2] + g3 * b2s[3 * DD + c0 + 2];
        o.w = v.w + v1.w + hv.w
            + g0 * b2s[c0 + 3] + g1 * b2s[DD + c0 + 3] + g2 * b2s[2 * DD + c0 + 3] + g3 * b2s[3 * DD + c0 + 3];
        vals[i] = o;
        s.x += o.x; s.y += o.y; s.z += o.z; s.w += o.w;
        q.x += o.x * o.x; q.y += o.y * o.y; q.z += o.z * o.z; q.w += o.w * o.w;
    }
    __shared__ float4 sS[8][32], sQ[8][32];
    sS[rg][c4] = s; sQ[rg][c4] = q;
    __syncthreads();
    if (threadIdx.x < 32) {
        float4 ts = make_float4(0.f, 0.f, 0.f, 0.f), tq = ts;
        #pragma unroll
        for (int i = 0; i < 8; i++) {
            float4 a = sS[i][threadIdx.x], bq = sQ[i][threadIdx.x];
            ts.x += a.x; ts.y += a.y; ts.z += a.z; ts.w += a.w;
            tq.x += bq.x; tq.y += bq.y; tq.z += bq.z; tq.w += bq.w;
        }
        float* p = part + (long)(b * 16 + chunk) * 256;
        *(float4*)(p + (threadIdx.x << 2)) = ts;
        *(float4*)(p + 128 + (threadIdx.x << 2)) = tq;
    }
    __syncthreads();
    __threadfence();

    __shared__ int lastS;
    if (threadIdx.x == 0)
        lastS = (atomicAdd(&g_cntB[b], 1) == 15);
    __syncthreads();

    if (lastS) {
        if (threadIdx.x < DD) {
            const int d = threadIdx.x;
            float ss = 0.f, qq = 0.f;
            for (int c = 0; c < 16; c++) {
                const float* p = part + (long)(b * 16 + c) * 256;
                ss += p[d]; qq += p[128 + d];
            }
            float mean = ss * (1.f / 1024.f);
            float var  = qq * (1.f / 1024.f) - mean * mean;
            float inv  = rsqrtf(var + 1e-5f);
            float sc = n2w[d] * inv;
            g_nrm[b * 256 + d]       = sc;
            g_nrm[b * 256 + 128 + d] = n2b[d] - mean * sc;
        }
        __threadfence();
        __syncthreads();
        if (threadIdx.x == 0)
            atomicExch(&g_flagB[b], 1);
    } else {
        if (threadIdx.x == 0)
            while (atomicAdd(&g_flagB[b], 0) == 0) { }
        __syncthreads();
        __threadfence();
    }

    float sc[4], sf[4];
    #pragma unroll
    for (int jj = 0; jj < 4; jj++) {
        sc[jj] = g_nrm[b * 256 + c0 + jj];
        sf[jj] = g_nrm[b * 256 + 128 + c0 + jj];
    }
    #pragma unroll
    for (int i = 0; i < 8; i++) {
        const int r = rg + i * 8;
        float4 o = vals[i];
        o.x = o.x * sc[0] + sf[0];
        o.y = o.y * sc[1] + sf[1];
        o.z = o.z * sc[2] + sf[2];
        o.w = o.w * sc[3] + sf[3];
        *(float4*)(out + (row0 + r) * DD + c0) = o;
    }

    __threadfence();
    __syncthreads();
    if (threadIdx.x == 0) {
        if (atomicAdd(&g_cnt2, 1) == 127) {
            #pragma unroll
            for (int bb = 0; bb < BB; bb++) { g_cntB[bb] = 0; g_flagB[bb] = 0; }
            g_cnt2 = 0;
        }
    }
}

// ============================================================================
// Launch (5 kernels)
// ============================================================================
extern "C" void kernel_launch(void* const* d_in, const int* in_sizes, int n_in,
                              void* d_out, int out_size)
{
    const float* x     = (const float*)d_in[0];
    const float* Wqkv  = (const float*)d_in[1];
    const float* bqkv  = (const float*)d_in[2];
    const float* Wo    = (const float*)d_in[3];
    const float* bo    = (const float*)d_in[4];
    const float* n1w   = (const float*)d_in[5];
    const float* n1b   = (const float*)d_in[6];
    const float* n2w   = (const float*)d_in[7];
    const float* n2b   = (const float*)d_in[8];
    const float* wg    = (const float*)d_in[9];
    const float* W1    = (const float*)d_in[10];
    const float* b1    = (const float*)d_in[11];
    const float* W2    = (const float*)d_in[12];
    const float* b2    = (const float*)d_in[13];

    float *qkv, *oB, *oS, *pre1, *h, *gates, *ypart;
    float *wqkvB, *woB, *woS, *part;
    __nv_bfloat16 *w1bf, *w2bf;
    cudaGetSymbolAddress((void**)&qkv,   g_qkv);
    cudaGetSymbolAddress((void**)&oB,    g_oB);
    cudaGetSymbolAddress((void**)&oS,    g_oS);
    cudaGetSymbolAddress((void**)&pre1,  g_pre1);
    cudaGetSymbolAddress((void**)&h,     g_h);
    cudaGetSymbolAddress((void**)&gates, g_gates);
    cudaGetSymbolAddress((void**)&ypart, g_ypart);
    cudaGetSymbolAddress((void**)&w1bf,  g_w1bf);
    cudaGetSymbolAddress((void**)&w2bf,  g_w2bf);
    cudaGetSymbolAddress((void**)&wqkvB, g_wqkvB);
    cudaGetSymbolAddress((void**)&woB,   g_woB);
    cudaGetSymbolAddress((void**)&woS,   g_woS);
    cudaGetSymbolAddress((void**)&part,  g_part);

    cudaFuncSetAttribute(attn_mma, cudaFuncAttributeMaxDynamicSharedMemorySize, ATTN_SMEM);
    cudaFuncSetAttribute(qkv_fused, cudaFuncAttributeMaxDynamicSharedMemorySize, 46080);
    cudaFuncSetAttribute(gemm_mma3, cudaFuncAttributeMaxDynamicSharedMemorySize, 92160);
    cudaFuncSetAttribute(moe_fused, cudaFuncAttributeMaxDynamicSharedMemorySize, MOE_SMEM);

    // 0. Wqkv prep
    weight_prep<<<48, 256>>>(Wqkv, wqkvB);

    // 1. FUSED: QKV projection (1xTF32, 3-stage) + Wo/W1/W2 transposes
    qkv_fused<<<912, 256, 46080>>>(x, wqkvB, bqkv, qkv,
                                   Wo, W1, W2, woB, woS, w1bf, w2bf);

    // 2. MMA flash attention
    attn_mma<<<dim3(64, 2), 256, ATTN_SMEM>>>(qkv, oB, oS);

    // 3. O-projection + bo + residual x ⊕ norm-1 stats (3xTF32, BM=64, 3-stage)
    gemm_mma3<<<dim3(1, 128), 256, 92160>>>(oB, oS, woB, woS, bo, x, pre1,
                                            128, 128, 128, 8, 128, part);

    // 4. FUSED MoE ⊕ norm-1 apply ⊕ gating
    moe_fused<<<dim3(128, 2), 256, MOE_SMEM>>>(pre1, part, n1w, n1b, wg,
                                               w1bf, w2bf, b1, h, gates, ypart);

    // 5. FUSED final: add + norm-2 stats + per-batch grid-sync + apply -> output
    add_norm2<<<dim3(16, 8), 256>>>(ypart, h, gates, b2, n2w, n2b,
                                    part, (float*)d_out);
}